// round 17
// baseline (speedup 1.0000x reference)
#include <cuda_runtime.h>
#include <cuda_bf16.h>

// Scratch (allocation-free rule: __device__ globals, zero-initialized at load).
#define MAX_N 131072
__device__ float g_diag[MAX_N];   // sigmoid(x@w + b) per node
__device__ float g_deg[MAX_N];    // INVARIANT: all-zero at kernel_launch entry;
                                  // deg accumulates, inv_kernel rezeroes.
__device__ float g_dinv[MAX_N];   // 1/deg
__device__ int   g_is64;          // only used by the rare hedge output paths

// ---------------------------------------------------------------------------
// WARP-PARALLEL dtype probe: lanes 0..15 each load ONE leading int64 entry;
// ballot combines. One memory round-trip (vs 16 serial), no smem, no barrier.
// All-in-[0,N) is impossible for reinterpreted int32 pairs (P ~ 1e-80).
// Must be called by all 32 lanes of a warp.
// ---------------------------------------------------------------------------
__device__ __forceinline__ int probe_is64_warp(const void* __restrict__ ei,
                                               long long N, int E) {
    int lane = threadIdx.x & 31;
    int cnt = E < 16 ? (E < 1 ? 1 : E) : 16;
    int bad = 0;
    if (lane < cnt) {
        long long v = __ldg((const long long*)ei + lane);
        bad = (v < 0 || v >= N) ? 1 : 0;
    }
    return __ballot_sync(0xFFFFFFFFu, bad) == 0;
}

// Single-thread version for the rare hedge path only.
__device__ __forceinline__ int probe_is64_once(const void* __restrict__ ei,
                                               long long N, int E) {
    const long long* p = (const long long*)ei;
    int cnt = E < 16 ? (E < 1 ? 1 : E) : 16;
    int ok = 1;
    for (int i = 0; i < cnt; ++i) {
        long long v = __ldg(p + i);
        if (v < 0 || v >= N) ok = 0;
    }
    return ok;
}

// ---------------------------------------------------------------------------
// Kernel 1 (2-role FUSED): deg CTAs + diag CTAs interleaved in one grid.
//  - deg CTAs (bid % f == 0): histogram col into g_deg via float atomics
//    (exact & order-independent for counts < 2^24 -> deterministic).
//    g_deg is zero at entry by the zero-at-exit invariant.
//  - diag CTAs (others): warp-per-row  diag[i] = sigmoid(x[i]·w + b).
// Interleave co-schedules DRAM-streaming (diag) with L2-atomic (deg) work.
// ---------------------------------------------------------------------------
__global__ void __launch_bounds__(256)
fused_diag_deg(const float* __restrict__ x,
               const float* __restrict__ w,
               const float* __restrict__ bb,
               const void* __restrict__ eiv,
               int N, int D, int E,
               int nDiag, int nDeg, int f) {
    int bid = blockIdx.x;
    int tid = threadIdx.x;

    if (bid % f == 0) {
        // ---- degree CTA ----
        int degIdx = bid / f;
        if (degIdx >= nDeg) return;
        const int is64 = probe_is64_warp(eiv, N, E);   // per-warp, 1 round-trip
        int e = (degIdx * blockDim.x + tid) * 8;
        if (is64) {
            const long long* col = (const long long*)eiv + E;   // second row
            if (e + 8 <= E) {
                longlong2 c0 = __ldcs((const longlong2*)(col + e));
                longlong2 c1 = __ldcs((const longlong2*)(col + e + 2));
                longlong2 c2 = __ldcs((const longlong2*)(col + e + 4));
                longlong2 c3 = __ldcs((const longlong2*)(col + e + 6));
                atomicAdd(&g_deg[(int)c0.x], 1.0f);
                atomicAdd(&g_deg[(int)c0.y], 1.0f);
                atomicAdd(&g_deg[(int)c1.x], 1.0f);
                atomicAdd(&g_deg[(int)c1.y], 1.0f);
                atomicAdd(&g_deg[(int)c2.x], 1.0f);
                atomicAdd(&g_deg[(int)c2.y], 1.0f);
                atomicAdd(&g_deg[(int)c3.x], 1.0f);
                atomicAdd(&g_deg[(int)c3.y], 1.0f);
            } else {
                for (; e < E; ++e) atomicAdd(&g_deg[(int)col[e]], 1.0f);
            }
        } else {
            const int* col = (const int*)eiv + E;
            if (e + 8 <= E) {
                int4 c0 = __ldcs((const int4*)(col + e));
                int4 c1 = __ldcs((const int4*)(col + e + 4));
                atomicAdd(&g_deg[c0.x], 1.0f);
                atomicAdd(&g_deg[c0.y], 1.0f);
                atomicAdd(&g_deg[c0.z], 1.0f);
                atomicAdd(&g_deg[c0.w], 1.0f);
                atomicAdd(&g_deg[c1.x], 1.0f);
                atomicAdd(&g_deg[c1.y], 1.0f);
                atomicAdd(&g_deg[c1.z], 1.0f);
                atomicAdd(&g_deg[c1.w], 1.0f);
            } else {
                for (; e < E; ++e) atomicAdd(&g_deg[col[e]], 1.0f);
            }
        }
        return;
    }

    // ---- diag CTA: warp-per-row dot product ----
    int diagIdx = bid - bid / f - 1;
    if (diagIdx >= nDiag) return;
    int warpInBlk = tid >> 5;
    int lane = tid & 31;
    int row = diagIdx * (blockDim.x >> 5) + warpInBlk;
    if (row >= N) return;

    const float4* xr = (const float4*)(x + (size_t)row * D);
    const float4* wv = (const float4*)w;
    int nvec = D >> 2;               // float4s per row (64 for D=256)
    float s = 0.0f;
    #pragma unroll 2
    for (int i = lane; i < nvec; i += 32) {
        float4 a  = __ldcs(&xr[i]);   // streaming: don't pollute L2
        float4 ww = wv[i];            // tiny, reused: default caching
        s += a.x * ww.x + a.y * ww.y + a.z * ww.z + a.w * ww.w;
    }
    #pragma unroll
    for (int o = 16; o; o >>= 1) s += __shfl_xor_sync(0xFFFFFFFFu, s, o);

    if (lane == 0) {
        float z = s + bb[0];
        g_diag[row] = 1.0f / (1.0f + __expf(-z));
    }
}

// ---------------------------------------------------------------------------
// Kernel 2: g_dinv = 1/g_deg, and REZERO g_deg (restores the zero-at-entry
// invariant for the next graph replay). 1/0 -> inf matches torch deg.pow(-1).
// ---------------------------------------------------------------------------
__global__ void __launch_bounds__(256) inv_kernel(int N) {
    int i = (blockIdx.x * blockDim.x + threadIdx.x) * 4;
    if (i + 4 <= N) {
        float4 v = *(float4*)(g_deg + i);
        float4 r;
        r.x = 1.0f / v.x; r.y = 1.0f / v.y;
        r.z = 1.0f / v.z; r.w = 1.0f / v.w;
        *(float4*)(g_dinv + i) = r;
        *(float4*)(g_deg + i)  = make_float4(0.f, 0.f, 0.f, 0.f);
    } else {
        for (; i < N; ++i) {
            g_dinv[i] = 1.0f / g_deg[i];
            g_deg[i]  = 0.0f;
        }
    }
}

// ---------------------------------------------------------------------------
// Kernel 3 (val + FUSED CAST): per edge e,
//   out[e] = g_dinv[row[e]] * attr[e] * g_diag[col[e]]
// and, when castOut != nullptr (flattened-tuple layout),
//   castOut[e] = (float)row[e];  castOut[E+e] = (float)col[e]
// — the indices are ALREADY in registers, so the cast costs zero extra reads.
// 8 edges/thread, front-batched loads; streams via __ldcs/__stcs keep the
// 1.2 MB gather tables L2-resident. Warp-parallel dtype probe.
// ---------------------------------------------------------------------------
__global__ void __launch_bounds__(256)
val_kernel(const void* __restrict__ eiv,
           const float* __restrict__ attr,
           float* __restrict__ castOut,
           float* __restrict__ out, int N, int E) {
    const int is64 = probe_is64_warp(eiv, N, E);
    int tid = threadIdx.x;
    int e = (blockIdx.x * blockDim.x + tid) * 8;
    const bool colVecOK = ((E & 3) == 0);   // alignment of castOut+E for float4

    if (is64) {
        const long long* row = (const long long*)eiv;
        const long long* col = row + E;
        if (e + 8 <= E) {
            longlong2 r0 = __ldcs((const longlong2*)(row + e));
            longlong2 r1 = __ldcs((const longlong2*)(row + e + 2));
            longlong2 r2 = __ldcs((const longlong2*)(row + e + 4));
            longlong2 r3 = __ldcs((const longlong2*)(row + e + 6));
            longlong2 c0 = __ldcs((const longlong2*)(col + e));
            longlong2 c1 = __ldcs((const longlong2*)(col + e + 2));
            longlong2 c2 = __ldcs((const longlong2*)(col + e + 4));
            longlong2 c3 = __ldcs((const longlong2*)(col + e + 6));
            float4 a0 = __ldcs((const float4*)(attr + e));
            float4 a1 = __ldcs((const float4*)(attr + e + 4));
            float4 v0, v1;
            v0.x = g_dinv[(int)r0.x] * a0.x * g_diag[(int)c0.x];
            v0.y = g_dinv[(int)r0.y] * a0.y * g_diag[(int)c0.y];
            v0.z = g_dinv[(int)r1.x] * a0.z * g_diag[(int)c1.x];
            v0.w = g_dinv[(int)r1.y] * a0.w * g_diag[(int)c1.y];
            v1.x = g_dinv[(int)r2.x] * a1.x * g_diag[(int)c2.x];
            v1.y = g_dinv[(int)r2.y] * a1.y * g_diag[(int)c2.y];
            v1.z = g_dinv[(int)r3.x] * a1.z * g_diag[(int)c3.x];
            v1.w = g_dinv[(int)r3.y] * a1.w * g_diag[(int)c3.y];
            __stcs((float4*)(out + e),     v0);
            __stcs((float4*)(out + e + 4), v1);
            if (castOut) {
                __stcs((float4*)(castOut + e),
                       make_float4((float)r0.x, (float)r0.y,
                                   (float)r1.x, (float)r1.y));
                __stcs((float4*)(castOut + e + 4),
                       make_float4((float)r2.x, (float)r2.y,
                                   (float)r3.x, (float)r3.y));
                if (colVecOK) {
                    __stcs((float4*)(castOut + E + e),
                           make_float4((float)c0.x, (float)c0.y,
                                       (float)c1.x, (float)c1.y));
                    __stcs((float4*)(castOut + E + e + 4),
                           make_float4((float)c2.x, (float)c2.y,
                                       (float)c3.x, (float)c3.y));
                } else {
                    castOut[E + e]     = (float)c0.x;
                    castOut[E + e + 1] = (float)c0.y;
                    castOut[E + e + 2] = (float)c1.x;
                    castOut[E + e + 3] = (float)c1.y;
                    castOut[E + e + 4] = (float)c2.x;
                    castOut[E + e + 5] = (float)c2.y;
                    castOut[E + e + 6] = (float)c3.x;
                    castOut[E + e + 7] = (float)c3.y;
                }
            }
        } else {
            for (; e < E; ++e) {
                long long r = row[e], c = col[e];
                out[e] = g_dinv[(int)r] * attr[e] * g_diag[(int)c];
                if (castOut) {
                    castOut[e]     = (float)r;
                    castOut[E + e] = (float)c;
                }
            }
        }
    } else {
        const int* row = (const int*)eiv;
        const int* col = row + E;
        if (e + 8 <= E) {
            int4 r0 = __ldcs((const int4*)(row + e));
            int4 r1 = __ldcs((const int4*)(row + e + 4));
            int4 c0 = __ldcs((const int4*)(col + e));
            int4 c1 = __ldcs((const int4*)(col + e + 4));
            float4 a0 = __ldcs((const float4*)(attr + e));
            float4 a1 = __ldcs((const float4*)(attr + e + 4));
            float4 v0, v1;
            v0.x = g_dinv[r0.x] * a0.x * g_diag[c0.x];
            v0.y = g_dinv[r0.y] * a0.y * g_diag[c0.y];
            v0.z = g_dinv[r0.z] * a0.z * g_diag[c0.z];
            v0.w = g_dinv[r0.w] * a0.w * g_diag[c0.w];
            v1.x = g_dinv[r1.x] * a1.x * g_diag[c1.x];
            v1.y = g_dinv[r1.y] * a1.y * g_diag[c1.y];
            v1.z = g_dinv[r1.z] * a1.z * g_diag[c1.z];
            v1.w = g_dinv[r1.w] * a1.w * g_diag[c1.w];
            __stcs((float4*)(out + e),     v0);
            __stcs((float4*)(out + e + 4), v1);
            if (castOut) {
                __stcs((float4*)(castOut + e),
                       make_float4((float)r0.x, (float)r0.y,
                                   (float)r0.z, (float)r0.w));
                __stcs((float4*)(castOut + e + 4),
                       make_float4((float)r1.x, (float)r1.y,
                                   (float)r1.z, (float)r1.w));
                if (colVecOK) {
                    __stcs((float4*)(castOut + E + e),
                           make_float4((float)c0.x, (float)c0.y,
                                       (float)c0.z, (float)c0.w));
                    __stcs((float4*)(castOut + E + e + 4),
                           make_float4((float)c1.x, (float)c1.y,
                                       (float)c1.z, (float)c1.w));
                } else {
                    castOut[E + e]     = (float)c0.x;
                    castOut[E + e + 1] = (float)c0.y;
                    castOut[E + e + 2] = (float)c0.z;
                    castOut[E + e + 3] = (float)c0.w;
                    castOut[E + e + 4] = (float)c1.x;
                    castOut[E + e + 5] = (float)c1.y;
                    castOut[E + e + 6] = (float)c1.z;
                    castOut[E + e + 7] = (float)c1.w;
                }
            }
        } else {
            for (; e < E; ++e) {
                int r = row[e], c = col[e];
                out[e] = g_dinv[r] * attr[e] * g_diag[c];
                if (castOut) {
                    castOut[e]     = (float)r;
                    castOut[E + e] = (float)c;
                }
            }
        }
    }
}

// ---------------------------------------------------------------------------
// Hedge-path kernels (only launched for unexpected out_size layouts).
// ---------------------------------------------------------------------------
__global__ void probe_kernel(const void* __restrict__ ei, int N, int E) {
    g_is64 = probe_is64_once(ei, N, E);
}

__global__ void idx_copy_kernel(const void* __restrict__ src,
                                void* __restrict__ dst, int n2e) {
    const int is64 = g_is64;
    int i = (blockIdx.x * blockDim.x + threadIdx.x) * 4;
    if (is64) {
        const long long* s = (const long long*)src;
        long long* d = (long long*)dst;
        if (i + 4 <= n2e) {
            *(longlong2*)(d + i)     = *(const longlong2*)(s + i);
            *(longlong2*)(d + i + 2) = *(const longlong2*)(s + i + 2);
        } else {
            for (; i < n2e; ++i) d[i] = s[i];
        }
    } else {
        const int* s = (const int*)src;
        int* d = (int*)dst;
        if (i + 4 <= n2e) {
            *(int4*)(d + i) = *(const int4*)(s + i);
        } else {
            for (; i < n2e; ++i) d[i] = s[i];
        }
    }
}

extern "C" void kernel_launch(void* const* d_in, const int* in_sizes, int n_in,
                              void* d_out, int out_size) {
    const float* x    = (const float*)d_in[0];
    const void*  ei   = d_in[1];                 // [2, E] int32 or int64
    const float* attr = (const float*)d_in[2];
    const float* w    = (const float*)d_in[3];
    const float* b    = (const float*)d_in[4];

    int D = in_sizes[3];
    int N = in_sizes[0] / D;
    int E = in_sizes[2];

    const int threads = 256;

    // Indices-only layout hedge (no values) — separate simple path.
    if (out_size == 2 * E) {
        probe_kernel<<<1, 1>>>(ei, N, E);
        int n2e = 2 * E;
        int work = (n2e + 3) / 4;
        int blocks = (work + threads - 1) / threads;
        idx_copy_kernel<<<blocks, threads>>>(ei, d_out, n2e);
        return;
    }

    const bool tuple = (out_size == 3 * E);   // flattened (idx-as-float, vals)
    float* castOut = tuple ? (float*)d_out : nullptr;
    float* val_out = tuple ? (float*)d_out + 2 * E : (float*)d_out;

    // Stage 1 (2-role fused): diag + degree in one interleaved grid.
    {
        int warpsPerBlock = threads / 32;                  // 8 rows per CTA
        int nDiag = (N + warpsPerBlock - 1) / warpsPerBlock;
        int edgesPerCTA = threads * 8;
        int nDeg = (E + edgesPerCTA - 1) / edgesPerCTA;
        int total = nDiag + nDeg;
        int f = (total + nDeg - 1) / nDeg;                 // interleave stride
        int grid = total + f;                              // spares guarded
        fused_diag_deg<<<grid, threads>>>(x, w, b, ei, N, D, E,
                                          nDiag, nDeg, f);
    }
    // Stage 2: invert degree + rezero g_deg (restores invariant for replay).
    {
        int work = (N + 3) / 4;
        int blocks = (work + threads - 1) / threads;
        inv_kernel<<<blocks, threads>>>(N);
    }
    // Stage 3: values + fused index cast (zero extra reads).
    {
        int work = (E + 7) / 8;
        int blocks = (work + threads - 1) / threads;
        val_kernel<<<blocks, threads>>>(ei, attr, castOut, val_out, N, E);
    }
}